// round 2
// baseline (speedup 1.0000x reference)
#include <cuda_runtime.h>
#include <cstdint>

#define N_NODES 100000
#define E_EDGES 1280000
#define C_IN    64
#define MID     256
#define OUT_F   64
#define BN_EPS  1e-5f

// ---------------- scratch (static device memory; no runtime allocation) ----
__device__ float g_sums[(size_t)N_NODES * 128];   // [N][128]: [sum_x | sum_x*ea]
__device__ float g_cnt[N_NODES];
__device__ float g_colsum[MID];
__device__ float g_colsumsq[MID];
__device__ float g_h[(size_t)N_NODES * MID];      // relu(agg@W1+b1)
__device__ float g_W2p[MID * OUT_F];              // s-scaled W2
__device__ float g_b2p[OUT_F];
__device__ int   g_idx64;                         // 1 if edge_index is int64

// ---------------- dtype probe: int64 vs int32 edge_index -------------------
// int64 values < 2^31 stored little-endian => odd 32-bit words are all zero.
// Random int32 node ids in [0,100000) are ~never zero at 16 consecutive odd
// positions, so this is a robust discriminator.
__global__ void detect_kernel(const int* __restrict__ ei32) {
    if (threadIdx.x == 0) {
        int all_zero = 1;
        #pragma unroll
        for (int i = 0; i < 16; i++)
            if (ei32[2 * i + 1] != 0) all_zero = 0;
        g_idx64 = all_zero;
    }
}

// ---------------- edge scatter: one warp per edge -------------------------
__global__ void edge_kernel(const float* __restrict__ x,
                            const void* __restrict__ ei,
                            const float* __restrict__ ea) {
    int e = (blockIdx.x * blockDim.x + threadIdx.x) >> 5;
    int lane = threadIdx.x & 31;
    if (e >= E_EDGES) return;
    int row, col;
    if (g_idx64) {
        const long long* p = (const long long*)ei;
        row = (int)p[e];
        col = (int)p[E_EDGES + e];
    } else {
        const int* p = (const int*)ei;
        row = p[e];
        col = p[E_EDGES + e];
    }
    if ((unsigned)row >= N_NODES || (unsigned)col >= N_NODES) return; // safety
    float a = ea[e];
    const float* xr = x + (size_t)col * C_IN;
    float v0 = xr[lane];
    float v1 = xr[lane + 32];
    float* s = g_sums + (size_t)row * 128;
    atomicAdd(s + lane,       v0);
    atomicAdd(s + lane + 32,  v1);
    atomicAdd(s + lane + 64,  v0 * a);
    atomicAdd(s + lane + 96,  v1 * a);
    if (lane == 0) atomicAdd(&g_cnt[row], 1.0f);
}

// ---------------- GEMM1: h = relu(agg@W1 + b1), fused BN stats -------------
// Block tile 128(M) x 128(N), full K=128 in smem. 256 threads, 8x8 per thread.
// As stored k-major [128][132] (pitch 132 -> conflict-free float4 compute reads).
#define G1_SMEM_FLOATS (128*132 + 128*128 + 128)
__global__ __launch_bounds__(256, 1)
void gemm1_kernel(const float* __restrict__ W1, const float* __restrict__ b1) {
    extern __shared__ float sm[];
    float* As   = sm;               // [k=128][m pitch 132]
    float* Bs   = sm + 128 * 132;   // [k=128][n=128]
    float* invs = Bs + 128 * 128;   // [128]
    __shared__ float ssum[128], ssq[128];

    int tid = threadIdx.x;
    int rowbase = blockIdx.x * 128;
    int colbase = blockIdx.y * 128;

    if (tid < 128) {
        ssum[tid] = 0.f; ssq[tid] = 0.f;
        int r = rowbase + tid;
        float c = (r < N_NODES) ? g_cnt[r] : 1.f;
        invs[tid] = 1.f / fmaxf(c, 1.f);
    }
    __syncthreads();

    // A: agg tile (divide-by-count applied on load), transposed into smem.
    #pragma unroll
    for (int i = 0; i < 64; i++) {
        int idx = i * 256 + tid;
        int m = idx >> 7;
        int k = idx & 127;
        int r = rowbase + m;
        float v = (r < N_NODES) ? g_sums[(size_t)r * 128 + k] * invs[m] : 0.f;
        As[k * 132 + m] = v;
    }
    // B: W1 tile, straight float4 copy (conflict-free).
    #pragma unroll
    for (int i = 0; i < 16; i++) {
        int idx = i * 256 + tid;
        int k = idx >> 5;
        int c4 = idx & 31;
        *(float4*)&Bs[k * 128 + c4 * 4] =
            *(const float4*)&W1[(size_t)k * MID + colbase + c4 * 4];
    }
    __syncthreads();

    int warp = tid >> 5, lane = tid & 31;
    int warpM = warp & 3, warpN = warp >> 2;      // warps 4x2
    int mp = lane >> 3,  np = lane & 7;           // lanes 4x8
    int tm = warpM * 32 + mp * 8;
    int tn = warpN * 64 + np * 8;

    float acc[8][8];
    #pragma unroll
    for (int i = 0; i < 8; i++)
        #pragma unroll
        for (int j = 0; j < 8; j++) acc[i][j] = 0.f;

    #pragma unroll 4
    for (int k = 0; k < 128; k++) {
        float4 a0 = *(const float4*)&As[k * 132 + tm];
        float4 a1 = *(const float4*)&As[k * 132 + tm + 4];
        float4 b0 = *(const float4*)&Bs[k * 128 + tn];
        float4 b1v = *(const float4*)&Bs[k * 128 + tn + 4];
        float ar[8] = {a0.x, a0.y, a0.z, a0.w, a1.x, a1.y, a1.z, a1.w};
        float br[8] = {b0.x, b0.y, b0.z, b0.w, b1v.x, b1v.y, b1v.z, b1v.w};
        #pragma unroll
        for (int i = 0; i < 8; i++)
            #pragma unroll
            for (int j = 0; j < 8; j++) acc[i][j] = fmaf(ar[i], br[j], acc[i][j]);
    }

    // epilogue: +b1, relu, store h, per-block column sum/sumsq
    float bb[8];
    #pragma unroll
    for (int j = 0; j < 8; j++) bb[j] = b1[colbase + tn + j];

    float s_[8], q_[8];
    #pragma unroll
    for (int j = 0; j < 8; j++) { s_[j] = 0.f; q_[j] = 0.f; }

    #pragma unroll
    for (int i = 0; i < 8; i++) {
        int r = rowbase + tm + i;
        float v[8];
        #pragma unroll
        for (int j = 0; j < 8; j++) v[j] = fmaxf(acc[i][j] + bb[j], 0.f);
        if (r < N_NODES) {
            float* hp = &g_h[(size_t)r * MID + colbase + tn];
            *(float4*)hp       = make_float4(v[0], v[1], v[2], v[3]);
            *(float4*)(hp + 4) = make_float4(v[4], v[5], v[6], v[7]);
            #pragma unroll
            for (int j = 0; j < 8; j++) { s_[j] += v[j]; q_[j] += v[j] * v[j]; }
        }
    }
    // reduce across the 4 mp lanes in each warp
    #pragma unroll
    for (int j = 0; j < 8; j++) {
        s_[j] += __shfl_xor_sync(0xFFFFFFFFu, s_[j], 8);
        s_[j] += __shfl_xor_sync(0xFFFFFFFFu, s_[j], 16);
        q_[j] += __shfl_xor_sync(0xFFFFFFFFu, q_[j], 8);
        q_[j] += __shfl_xor_sync(0xFFFFFFFFu, q_[j], 16);
    }
    if (mp == 0) {
        #pragma unroll
        for (int j = 0; j < 8; j++) {
            atomicAdd(&ssum[tn + j], s_[j]);
            atomicAdd(&ssq[tn + j],  q_[j]);
        }
    }
    __syncthreads();
    if (tid < 128) {
        atomicAdd(&g_colsum[colbase + tid],   ssum[tid]);
        atomicAdd(&g_colsumsq[colbase + tid], ssq[tid]);
    }
}

// ---------------- finalize: BN fold into W2', b2' --------------------------
__global__ void finalize_kernel(const float* __restrict__ gamma,
                                const float* __restrict__ beta,
                                const float* __restrict__ W2,
                                const float* __restrict__ b2) {
    __shared__ float s_sm[MID], t_sm[MID];
    int tid = threadIdx.x;  // 256
    float mu  = g_colsum[tid]   * (1.f / N_NODES);
    float var = g_colsumsq[tid] * (1.f / N_NODES) - mu * mu;
    float s = gamma[tid] * rsqrtf(var + BN_EPS);
    float t = beta[tid] - mu * s;
    s_sm[tid] = s; t_sm[tid] = t;
    __syncthreads();
    #pragma unroll
    for (int i = 0; i < 64; i++) {
        int idx = i * 256 + tid;            // 16384 = 256x64
        g_W2p[idx] = W2[idx] * s_sm[idx >> 6];
    }
    if (tid < OUT_F) {
        float acc = b2[tid];
        for (int j = 0; j < MID; j++) acc += t_sm[j] * W2[j * OUT_F + tid];
        g_b2p[tid] = acc;
    }
}

// ---------------- GEMM2: out = h @ W2p + b2p -------------------------------
// Block 128(M) x 64(N), full K=256 in smem. 256 threads, 8x4 per thread.
#define G2_SMEM_FLOATS (256*132 + 256*64 + 64)
__global__ __launch_bounds__(256, 1)
void gemm2_kernel(float* __restrict__ out) {
    extern __shared__ float sm[];
    float* As = sm;               // [k=256][m pitch 132]
    float* Bs = sm + 256 * 132;   // [k=256][n=64]
    float* bb = Bs + 256 * 64;    // [64]
    int tid = threadIdx.x;
    int rowbase = blockIdx.x * 128;

    // A: h tile transposed, float2 global reads (coalesced), scatter STS
    #pragma unroll
    for (int i = 0; i < 64; i++) {
        int idx = i * 256 + tid;
        int m = idx >> 7;
        int k2 = idx & 127;
        int r = rowbase + m;
        float2 v = (r < N_NODES) ? *(const float2*)&g_h[(size_t)r * MID + k2 * 2]
                                 : make_float2(0.f, 0.f);
        As[(k2 * 2)     * 132 + m] = v.x;
        As[(k2 * 2 + 1) * 132 + m] = v.y;
    }
    // B: W2p full, float4 copy
    #pragma unroll
    for (int i = 0; i < 16; i++) {
        int idx = i * 256 + tid;
        *(float4*)&Bs[idx * 4] = *(const float4*)&g_W2p[idx * 4];
    }
    if (tid < OUT_F) bb[tid] = g_b2p[tid];
    __syncthreads();

    int warp = tid >> 5, lane = tid & 31;
    int warpM = warp & 3, warpN = warp >> 2;    // 4x2, warp tile 32x32
    int mp = lane >> 3,  np = lane & 7;
    int tm = warpM * 32 + mp * 8;
    int tn = warpN * 32 + np * 4;

    float acc[8][4];
    #pragma unroll
    for (int i = 0; i < 8; i++)
        #pragma unroll
        for (int j = 0; j < 4; j++) acc[i][j] = 0.f;

    #pragma unroll 4
    for (int k = 0; k < 256; k++) {
        float4 a0 = *(const float4*)&As[k * 132 + tm];
        float4 a1 = *(const float4*)&As[k * 132 + tm + 4];
        float4 b0 = *(const float4*)&Bs[k * 64 + tn];
        float ar[8] = {a0.x, a0.y, a0.z, a0.w, a1.x, a1.y, a1.z, a1.w};
        float br[4] = {b0.x, b0.y, b0.z, b0.w};
        #pragma unroll
        for (int i = 0; i < 8; i++)
            #pragma unroll
            for (int j = 0; j < 4; j++) acc[i][j] = fmaf(ar[i], br[j], acc[i][j]);
    }

    float4 bv = make_float4(bb[tn], bb[tn + 1], bb[tn + 2], bb[tn + 3]);
    #pragma unroll
    for (int i = 0; i < 8; i++) {
        int r = rowbase + tm + i;
        if (r < N_NODES) {
            float4 o = make_float4(acc[i][0] + bv.x, acc[i][1] + bv.y,
                                   acc[i][2] + bv.z, acc[i][3] + bv.w);
            *(float4*)&out[(size_t)r * OUT_F + tn] = o;
        }
    }
}

// ---------------- launch ---------------------------------------------------
extern "C" void kernel_launch(void* const* d_in, const int* in_sizes, int n_in,
                              void* d_out, int out_size) {
    // ---- robust input binding by element count ----
    // counts: x=6,400,000  edge_index=2,560,000  edge_attr=1,280,000
    //         batch=100,000  W1=32,768  W2=16,384  b2=64  {b1,gamma,beta}=256
    int ix = -1, iei = -1, iea = -1, iW1 = -1, iW2 = -1, ib2 = -1;
    int p256[3]; int n256 = 0;
    for (int i = 0; i < n_in; i++) {
        switch (in_sizes[i]) {
            case 6400000: ix  = i; break;
            case 2560000: iei = i; break;
            case 1280000: iea = i; break;
            case 32768:   iW1 = i; break;
            case 16384:   iW2 = i; break;
            case 64:      ib2 = i; break;
            case 256:     if (n256 < 3) p256[n256++] = i; break;
            default: break; // batch (100000) unused
        }
    }
    // 256-trio disambiguation: insertion order (x first) -> b1, gamma, beta;
    // alphabetical order (W1 first) -> b1, beta, gamma.
    int ib1, igamma, ibeta;
    if (n_in > 0 && in_sizes[0] == 6400000) { ib1 = p256[0]; igamma = p256[1]; ibeta = p256[2]; }
    else                                    { ib1 = p256[0]; ibeta  = p256[1]; igamma = p256[2]; }

    const float* x     = (const float*)d_in[ix];
    const void*  ei    = d_in[iei];
    const float* ea    = (const float*)d_in[iea];
    const float* W1    = (const float*)d_in[iW1];
    const float* b1    = (const float*)d_in[ib1];
    const float* gamma = (const float*)d_in[igamma];
    const float* beta  = (const float*)d_in[ibeta];
    const float* W2    = (const float*)d_in[iW2];
    const float* b2    = (const float*)d_in[ib2];
    float* out = (float*)d_out;

    cudaFuncSetAttribute(gemm1_kernel, cudaFuncAttributeMaxDynamicSharedMemorySize,
                         G1_SMEM_FLOATS * (int)sizeof(float));
    cudaFuncSetAttribute(gemm2_kernel, cudaFuncAttributeMaxDynamicSharedMemorySize,
                         G2_SMEM_FLOATS * (int)sizeof(float));

    void* p;
    cudaGetSymbolAddress(&p, g_sums);
    cudaMemsetAsync(p, 0, sizeof(float) * (size_t)N_NODES * 128);
    cudaGetSymbolAddress(&p, g_cnt);
    cudaMemsetAsync(p, 0, sizeof(float) * N_NODES);
    cudaGetSymbolAddress(&p, g_colsum);
    cudaMemsetAsync(p, 0, sizeof(float) * MID);
    cudaGetSymbolAddress(&p, g_colsumsq);
    cudaMemsetAsync(p, 0, sizeof(float) * MID);

    detect_kernel<<<1, 32>>>((const int*)ei);

    edge_kernel<<<E_EDGES / 8, 256>>>(x, ei, ea);

    dim3 g1((N_NODES + 127) / 128, MID / 128);
    gemm1_kernel<<<g1, 256, G1_SMEM_FLOATS * sizeof(float)>>>(W1, b1);

    finalize_kernel<<<1, 256>>>(gamma, beta, W2, b2);

    gemm2_kernel<<<(N_NODES + 127) / 128, 256, G2_SMEM_FLOATS * sizeof(float)>>>(out);
}

// round 3
// speedup vs baseline: 1.0297x; 1.0297x over previous
#include <cuda_runtime.h>
#include <cstdint>

#define N_NODES 100000
#define E_EDGES 1280000
#define C_IN    64
#define MID     256
#define OUT_F   64
#define BN_EPS  1e-5f

// ---------------- scratch (static device memory; no runtime allocation) ----
// One contiguous zero-region so a single memsetAsync clears everything.
#define ZR_SUMS    0
#define ZR_CNT     ((size_t)N_NODES * 128)
#define ZR_COLSUM  (ZR_CNT + N_NODES)
#define ZR_COLSQ   (ZR_COLSUM + MID)
#define ZR_TOTAL   (ZR_COLSQ + MID)
__device__ float g_zero[ZR_TOTAL];

__device__ float g_h[(size_t)N_NODES * MID];      // relu(agg@W1+b1)
__device__ float g_W2p[MID * OUT_F];              // s-scaled W2
__device__ float g_b2p[OUT_F];
__device__ int   g_idx64;                         // 1 if edge_index is int64

// ---------------- packed fp32 helpers (Blackwell FFMA2) --------------------
__device__ __forceinline__ unsigned long long dup2(float v) {
    unsigned long long r;
    asm("mov.b64 %0, {%1, %1};" : "=l"(r) : "f"(v));
    return r;
}
__device__ __forceinline__ void ffma2(unsigned long long& d,
                                      unsigned long long a,
                                      unsigned long long b) {
    asm("fma.rn.f32x2 %0, %1, %2, %0;" : "+l"(d) : "l"(a), "l"(b));
}
__device__ __forceinline__ void unpack2(unsigned long long v, float& lo, float& hi) {
    asm("mov.b64 {%0, %1}, %2;" : "=f"(lo), "=f"(hi) : "l"(v));
}

// ---------------- dtype probe: int64 vs int32 edge_index -------------------
__global__ void detect_kernel(const int* __restrict__ ei32) {
    if (threadIdx.x == 0) {
        int all_zero = 1;
        #pragma unroll
        for (int i = 0; i < 16; i++)
            if (ei32[2 * i + 1] != 0) all_zero = 0;
        g_idx64 = all_zero;
    }
}

// ---------------- edge scatter: one warp per edge -------------------------
__global__ void edge_kernel(const float* __restrict__ x,
                            const void* __restrict__ ei,
                            const float* __restrict__ ea) {
    int e = (blockIdx.x * blockDim.x + threadIdx.x) >> 5;
    int lane = threadIdx.x & 31;
    if (e >= E_EDGES) return;
    int row, col;
    if (g_idx64) {
        const long long* p = (const long long*)ei;
        row = (int)p[e];
        col = (int)p[E_EDGES + e];
    } else {
        const int* p = (const int*)ei;
        row = p[e];
        col = p[E_EDGES + e];
    }
    if ((unsigned)row >= N_NODES || (unsigned)col >= N_NODES) return; // safety
    float a = ea[e];
    const float* xr = x + (size_t)col * C_IN;
    float v0 = xr[lane];
    float v1 = xr[lane + 32];
    float* s = g_zero + ZR_SUMS + (size_t)row * 128;
    atomicAdd(s + lane,       v0);
    atomicAdd(s + lane + 32,  v1);
    atomicAdd(s + lane + 64,  v0 * a);
    atomicAdd(s + lane + 96,  v1 * a);
    if (lane == 0) atomicAdd(&g_zero[ZR_CNT + row], 1.0f);
}

// ---------------- GEMM1: h = relu(agg@W1 + b1), fused BN stats -------------
// Block tile 128(M) x 128(N), full K=128 in smem. 256 threads, 8x8 per thread.
// Inner loop uses fma.rn.f32x2: accumulators paired over m (A pairs come
// straight from the float4 smem loads; B operands duplicated via mov.b64).
#define G1_SMEM_FLOATS (128*132 + 128*128 + 128)
__global__ __launch_bounds__(256, 1)
void gemm1_kernel(const float* __restrict__ W1, const float* __restrict__ b1) {
    extern __shared__ float sm[];
    float* As   = sm;               // [k=128][m pitch 132]
    float* Bs   = sm + 128 * 132;   // [k=128][n=128]
    float* invs = Bs + 128 * 128;   // [128]
    __shared__ float ssum[128], ssq[128];

    int tid = threadIdx.x;
    int rowbase = blockIdx.x * 128;
    int colbase = blockIdx.y * 128;

    const float* g_sums = g_zero + ZR_SUMS;

    if (tid < 128) {
        ssum[tid] = 0.f; ssq[tid] = 0.f;
        int r = rowbase + tid;
        float c = (r < N_NODES) ? g_zero[ZR_CNT + r] : 1.f;
        invs[tid] = 1.f / fmaxf(c, 1.f);
    }
    __syncthreads();

    // A: agg tile (divide-by-count applied on load), transposed into smem.
    #pragma unroll
    for (int i = 0; i < 64; i++) {
        int idx = i * 256 + tid;
        int m = idx >> 7;
        int k = idx & 127;
        int r = rowbase + m;
        float v = (r < N_NODES) ? g_sums[(size_t)r * 128 + k] * invs[m] : 0.f;
        As[k * 132 + m] = v;
    }
    // B: W1 tile, straight float4 copy (conflict-free).
    #pragma unroll
    for (int i = 0; i < 16; i++) {
        int idx = i * 256 + tid;
        int k = idx >> 5;
        int c4 = idx & 31;
        *(float4*)&Bs[k * 128 + c4 * 4] =
            *(const float4*)&W1[(size_t)k * MID + colbase + c4 * 4];
    }
    __syncthreads();

    int warp = tid >> 5, lane = tid & 31;
    int warpM = warp & 3, warpN = warp >> 2;      // warps 4x2
    int mp = lane >> 3,  np = lane & 7;           // lanes 4x8
    int tm = warpM * 32 + mp * 8;
    int tn = warpN * 64 + np * 8;

    unsigned long long acc2[4][8];                // [m-pair][n]
    #pragma unroll
    for (int i = 0; i < 4; i++)
        #pragma unroll
        for (int j = 0; j < 8; j++) acc2[i][j] = 0ull;

    #pragma unroll 4
    for (int k = 0; k < 128; k++) {
        ulonglong2 A0 = *(const ulonglong2*)&As[k * 132 + tm];
        ulonglong2 A1 = *(const ulonglong2*)&As[k * 132 + tm + 4];
        unsigned long long ap[4] = {A0.x, A0.y, A1.x, A1.y};
        float4 b0 = *(const float4*)&Bs[k * 128 + tn];
        float4 b1v = *(const float4*)&Bs[k * 128 + tn + 4];
        unsigned long long bp[8] = {dup2(b0.x), dup2(b0.y), dup2(b0.z), dup2(b0.w),
                                    dup2(b1v.x), dup2(b1v.y), dup2(b1v.z), dup2(b1v.w)};
        #pragma unroll
        for (int i = 0; i < 4; i++)
            #pragma unroll
            for (int j = 0; j < 8; j++) ffma2(acc2[i][j], ap[i], bp[j]);
    }

    // unpack to scalar accs [m][n]
    float acc[8][8];
    #pragma unroll
    for (int i = 0; i < 4; i++)
        #pragma unroll
        for (int j = 0; j < 8; j++)
            unpack2(acc2[i][j], acc[2 * i][j], acc[2 * i + 1][j]);

    // epilogue: +b1, relu, store h, per-block column sum/sumsq
    float bb[8];
    #pragma unroll
    for (int j = 0; j < 8; j++) bb[j] = b1[colbase + tn + j];

    float s_[8], q_[8];
    #pragma unroll
    for (int j = 0; j < 8; j++) { s_[j] = 0.f; q_[j] = 0.f; }

    #pragma unroll
    for (int i = 0; i < 8; i++) {
        int r = rowbase + tm + i;
        float v[8];
        #pragma unroll
        for (int j = 0; j < 8; j++) v[j] = fmaxf(acc[i][j] + bb[j], 0.f);
        if (r < N_NODES) {
            float* hp = &g_h[(size_t)r * MID + colbase + tn];
            *(float4*)hp       = make_float4(v[0], v[1], v[2], v[3]);
            *(float4*)(hp + 4) = make_float4(v[4], v[5], v[6], v[7]);
            #pragma unroll
            for (int j = 0; j < 8; j++) { s_[j] += v[j]; q_[j] += v[j] * v[j]; }
        }
    }
    // reduce across the 4 mp lanes in each warp
    #pragma unroll
    for (int j = 0; j < 8; j++) {
        s_[j] += __shfl_xor_sync(0xFFFFFFFFu, s_[j], 8);
        s_[j] += __shfl_xor_sync(0xFFFFFFFFu, s_[j], 16);
        q_[j] += __shfl_xor_sync(0xFFFFFFFFu, q_[j], 8);
        q_[j] += __shfl_xor_sync(0xFFFFFFFFu, q_[j], 16);
    }
    if (mp == 0) {
        #pragma unroll
        for (int j = 0; j < 8; j++) {
            atomicAdd(&ssum[tn + j], s_[j]);
            atomicAdd(&ssq[tn + j],  q_[j]);
        }
    }
    __syncthreads();
    if (tid < 128) {
        atomicAdd(&g_zero[ZR_COLSUM + colbase + tid], ssum[tid]);
        atomicAdd(&g_zero[ZR_COLSQ  + colbase + tid], ssq[tid]);
    }
}

// ---------------- finalize: BN fold into W2', b2' --------------------------
__global__ void finalize_kernel(const float* __restrict__ gamma,
                                const float* __restrict__ beta,
                                const float* __restrict__ W2,
                                const float* __restrict__ b2) {
    __shared__ float s_sm[MID], t_sm[MID];
    int tid = threadIdx.x;  // 256
    float mu  = g_zero[ZR_COLSUM + tid] * (1.f / N_NODES);
    float var = g_zero[ZR_COLSQ  + tid] * (1.f / N_NODES) - mu * mu;
    float s = gamma[tid] * rsqrtf(var + BN_EPS);
    float t = beta[tid] - mu * s;
    s_sm[tid] = s; t_sm[tid] = t;
    __syncthreads();
    #pragma unroll
    for (int i = 0; i < 64; i++) {
        int idx = i * 256 + tid;            // 16384 = 256x64
        g_W2p[idx] = W2[idx] * s_sm[idx >> 6];
    }
    if (tid < OUT_F) {
        float acc = b2[tid];
        for (int j = 0; j < MID; j++) acc += t_sm[j] * W2[j * OUT_F + tid];
        g_b2p[tid] = acc;
    }
}

// ---------------- GEMM2: out = h @ W2p + b2p -------------------------------
// Block 128(M) x 64(N), full K=256 in smem. 256 threads, 8x4 per thread.
// Packed over m via fma.rn.f32x2.
#define G2_SMEM_FLOATS (256*132 + 256*64 + 64)
__global__ __launch_bounds__(256, 1)
void gemm2_kernel(float* __restrict__ out) {
    extern __shared__ float sm[];
    float* As = sm;               // [k=256][m pitch 132]
    float* Bs = sm + 256 * 132;   // [k=256][n=64]
    float* bb = Bs + 256 * 64;    // [64]
    int tid = threadIdx.x;
    int rowbase = blockIdx.x * 128;

    // A: h tile transposed, float2 global reads (coalesced), scatter STS
    #pragma unroll
    for (int i = 0; i < 64; i++) {
        int idx = i * 256 + tid;
        int m = idx >> 7;
        int k2 = idx & 127;
        int r = rowbase + m;
        float2 v = (r < N_NODES) ? *(const float2*)&g_h[(size_t)r * MID + k2 * 2]
                                 : make_float2(0.f, 0.f);
        As[(k2 * 2)     * 132 + m] = v.x;
        As[(k2 * 2 + 1) * 132 + m] = v.y;
    }
    // B: W2p full, float4 copy
    #pragma unroll
    for (int i = 0; i < 16; i++) {
        int idx = i * 256 + tid;
        *(float4*)&Bs[idx * 4] = *(const float4*)&g_W2p[idx * 4];
    }
    if (tid < OUT_F) bb[tid] = g_b2p[tid];
    __syncthreads();

    int warp = tid >> 5, lane = tid & 31;
    int warpM = warp & 3, warpN = warp >> 2;    // 4x2, warp tile 32x32
    int mp = lane >> 3,  np = lane & 7;
    int tm = warpM * 32 + mp * 8;
    int tn = warpN * 32 + np * 4;

    unsigned long long acc2[4][4];              // [m-pair][n]
    #pragma unroll
    for (int i = 0; i < 4; i++)
        #pragma unroll
        for (int j = 0; j < 4; j++) acc2[i][j] = 0ull;

    #pragma unroll 4
    for (int k = 0; k < 256; k++) {
        ulonglong2 A0 = *(const ulonglong2*)&As[k * 132 + tm];
        ulonglong2 A1 = *(const ulonglong2*)&As[k * 132 + tm + 4];
        unsigned long long ap[4] = {A0.x, A0.y, A1.x, A1.y};
        float4 b0 = *(const float4*)&Bs[k * 64 + tn];
        unsigned long long bp[4] = {dup2(b0.x), dup2(b0.y), dup2(b0.z), dup2(b0.w)};
        #pragma unroll
        for (int i = 0; i < 4; i++)
            #pragma unroll
            for (int j = 0; j < 4; j++) ffma2(acc2[i][j], ap[i], bp[j]);
    }

    float acc[8][4];
    #pragma unroll
    for (int i = 0; i < 4; i++)
        #pragma unroll
        for (int j = 0; j < 4; j++)
            unpack2(acc2[i][j], acc[2 * i][j], acc[2 * i + 1][j]);

    float4 bv = make_float4(bb[tn], bb[tn + 1], bb[tn + 2], bb[tn + 3]);
    #pragma unroll
    for (int i = 0; i < 8; i++) {
        int r = rowbase + tm + i;
        if (r < N_NODES) {
            float4 o = make_float4(acc[i][0] + bv.x, acc[i][1] + bv.y,
                                   acc[i][2] + bv.z, acc[i][3] + bv.w);
            *(float4*)&out[(size_t)r * OUT_F + tn] = o;
        }
    }
}

// ---------------- launch ---------------------------------------------------
extern "C" void kernel_launch(void* const* d_in, const int* in_sizes, int n_in,
                              void* d_out, int out_size) {
    // ---- robust input binding by element count ----
    int ix = -1, iei = -1, iea = -1, iW1 = -1, iW2 = -1, ib2 = -1;
    int p256[3]; int n256 = 0;
    for (int i = 0; i < n_in; i++) {
        switch (in_sizes[i]) {
            case 6400000: ix  = i; break;
            case 2560000: iei = i; break;
            case 1280000: iea = i; break;
            case 32768:   iW1 = i; break;
            case 16384:   iW2 = i; break;
            case 64:      ib2 = i; break;
            case 256:     if (n256 < 3) p256[n256++] = i; break;
            default: break; // batch (100000) unused
        }
    }
    int ib1, igamma, ibeta;
    if (n_in > 0 && in_sizes[0] == 6400000) { ib1 = p256[0]; igamma = p256[1]; ibeta = p256[2]; }
    else                                    { ib1 = p256[0]; ibeta  = p256[1]; igamma = p256[2]; }

    const float* x     = (const float*)d_in[ix];
    const void*  ei    = d_in[iei];
    const float* ea    = (const float*)d_in[iea];
    const float* W1    = (const float*)d_in[iW1];
    const float* b1    = (const float*)d_in[ib1];
    const float* gamma = (const float*)d_in[igamma];
    const float* beta  = (const float*)d_in[ibeta];
    const float* W2    = (const float*)d_in[iW2];
    const float* b2    = (const float*)d_in[ib2];
    float* out = (float*)d_out;

    cudaFuncSetAttribute(gemm1_kernel, cudaFuncAttributeMaxDynamicSharedMemorySize,
                         G1_SMEM_FLOATS * (int)sizeof(float));
    cudaFuncSetAttribute(gemm2_kernel, cudaFuncAttributeMaxDynamicSharedMemorySize,
                         G2_SMEM_FLOATS * (int)sizeof(float));

    void* p;
    cudaGetSymbolAddress(&p, g_zero);
    cudaMemsetAsync(p, 0, sizeof(float) * ZR_TOTAL);

    detect_kernel<<<1, 32>>>((const int*)ei);

    edge_kernel<<<E_EDGES / 8, 256>>>(x, ei, ea);

    dim3 g1((N_NODES + 127) / 128, MID / 128);
    gemm1_kernel<<<g1, 256, G1_SMEM_FLOATS * sizeof(float)>>>(W1, b1);

    finalize_kernel<<<1, 256>>>(gamma, beta, W2, b2);

    gemm2_kernel<<<(N_NODES + 127) / 128, 256, G2_SMEM_FLOATS * sizeof(float)>>>(out);
}

// round 4
// speedup vs baseline: 1.3395x; 1.3008x over previous
#include <cuda_runtime.h>
#include <cstdint>

#define N_NODES 100000
#define E_EDGES 1280000
#define C_IN    64
#define MID     256
#define OUT_F   64
#define BN_EPS  1e-5f

#define SCAN_BLK 512
#define SCAN_NB  ((N_NODES + SCAN_BLK - 1) / SCAN_BLK)   // 196

// ---------------- scratch (static device memory) ---------------------------
// zero-region (single memset): cnt[N] | off[N] | colsum[256] | colsq[256]
__device__ unsigned int g_zero[2 * N_NODES + 512];
#define P_CNT()    ((int*)g_zero)
#define P_OFF()    (((int*)g_zero) + N_NODES)
#define P_COLSUM() ((float*)(((int*)g_zero) + 2 * N_NODES))
#define P_COLSQ()  ((float*)(((int*)g_zero) + 2 * N_NODES + 256))

__device__ int   g_start[N_NODES + 1];            // CSR offsets
__device__ int   g_part[SCAN_NB];                 // scan partials
__device__ int   g_colS[E_EDGES];                 // row-sorted col
__device__ float g_aS[E_EDGES];                   // row-sorted edge_attr
__device__ float g_agg[(size_t)N_NODES * 128];    // mean-aggregated features
__device__ float g_h[(size_t)N_NODES * MID];      // relu(agg@W1+b1)
__device__ float g_W2p[MID * OUT_F];              // s-scaled W2
__device__ float g_b2p[OUT_F];
__device__ int   g_idx64;                         // 1 if edge_index is int64

// ---------------- packed fp32 helpers (Blackwell FFMA2) --------------------
__device__ __forceinline__ unsigned long long dup2(float v) {
    unsigned long long r;
    asm("mov.b64 %0, {%1, %1};" : "=l"(r) : "f"(v));
    return r;
}
__device__ __forceinline__ void ffma2(unsigned long long& d,
                                      unsigned long long a,
                                      unsigned long long b) {
    asm("fma.rn.f32x2 %0, %1, %2, %0;" : "+l"(d) : "l"(a), "l"(b));
}
__device__ __forceinline__ void unpack2(unsigned long long v, float& lo, float& hi) {
    asm("mov.b64 {%0, %1}, %2;" : "=f"(lo), "=f"(hi) : "l"(v));
}

// ---------------- dtype probe: int64 vs int32 edge_index -------------------
__global__ void detect_kernel(const int* __restrict__ ei32) {
    if (threadIdx.x == 0) {
        int all_zero = 1;
        #pragma unroll
        for (int i = 0; i < 16; i++)
            if (ei32[2 * i + 1] != 0) all_zero = 0;
        g_idx64 = all_zero;
    }
}

__device__ __forceinline__ int load_idx(const void* ei, size_t pos) {
    return g_idx64 ? (int)((const long long*)ei)[pos] : ((const int*)ei)[pos];
}

// ---------------- 1) histogram --------------------------------------------
__global__ void hist_kernel(const void* __restrict__ ei) {
    int e = blockIdx.x * blockDim.x + threadIdx.x;
    if (e >= E_EDGES) return;
    int row = load_idx(ei, e);
    if ((unsigned)row < N_NODES) atomicAdd(&P_CNT()[row], 1);
}

// ---------------- 2) two-level exclusive scan ------------------------------
__global__ void scanP_kernel() {
    __shared__ int sm[SCAN_BLK / 32];
    int idx = blockIdx.x * SCAN_BLK + threadIdx.x;
    int v = (idx < N_NODES) ? P_CNT()[idx] : 0;
    #pragma unroll
    for (int o = 16; o > 0; o >>= 1) v += __shfl_down_sync(0xFFFFFFFFu, v, o);
    if ((threadIdx.x & 31) == 0) sm[threadIdx.x >> 5] = v;
    __syncthreads();
    if (threadIdx.x < SCAN_BLK / 32) {
        int s = sm[threadIdx.x];
        #pragma unroll
        for (int o = SCAN_BLK / 64; o > 0; o >>= 1) s += __shfl_down_sync(0xFFFFFFFFu, s, o);
        if (threadIdx.x == 0) g_part[blockIdx.x] = s;
    }
}
__global__ void scanT_kernel() {
    __shared__ int sm[256];
    int tid = threadIdx.x;
    int v = (tid < SCAN_NB) ? g_part[tid] : 0;
    sm[tid] = v;
    __syncthreads();
    for (int o = 1; o < 256; o <<= 1) {
        int t = (tid >= o) ? sm[tid - o] : 0;
        __syncthreads();
        sm[tid] += t;
        __syncthreads();
    }
    if (tid < SCAN_NB) g_part[tid] = sm[tid] - v;   // exclusive
    if (tid == 255) g_start[N_NODES] = sm[255];     // total valid edges
}
__global__ void scanF_kernel() {
    __shared__ int sm[SCAN_BLK];
    int tid = threadIdx.x;
    int idx = blockIdx.x * SCAN_BLK + tid;
    int v = (idx < N_NODES) ? P_CNT()[idx] : 0;
    sm[tid] = v;
    __syncthreads();
    for (int o = 1; o < SCAN_BLK; o <<= 1) {
        int t = (tid >= o) ? sm[tid - o] : 0;
        __syncthreads();
        sm[tid] += t;
        __syncthreads();
    }
    if (idx < N_NODES) g_start[idx] = g_part[blockIdx.x] + sm[tid] - v;
}

// ---------------- 3) scatter into row-sorted order -------------------------
__global__ void scatter_kernel(const void* __restrict__ ei,
                               const float* __restrict__ ea) {
    int e = blockIdx.x * blockDim.x + threadIdx.x;
    if (e >= E_EDGES) return;
    int row = load_idx(ei, e);
    int col = load_idx(ei, (size_t)E_EDGES + e);
    if ((unsigned)row >= N_NODES || (unsigned)col >= N_NODES) return;
    int p = g_start[row] + atomicAdd(&P_OFF()[row], 1);
    g_colS[p] = col;
    g_aS[p]   = ea[e];
}

// ---------------- 4) warp-per-node gather aggregation ----------------------
__global__ __launch_bounds__(256)
void agg_kernel(const float* __restrict__ x) {
    int node = (blockIdx.x * blockDim.x + threadIdx.x) >> 5;
    int lane = threadIdx.x & 31;
    if (node >= N_NODES) return;
    int s = g_start[node];
    int e = g_start[node + 1];
    float v0 = 0.f, v1 = 0.f, w0 = 0.f, w1 = 0.f;
    for (int i = s; i < e; i++) {
        int col = g_colS[i];          // uniform across warp (broadcast)
        float a = g_aS[i];
        const float* xr = x + (size_t)col * C_IN;
        float x0 = xr[lane];
        float x1 = xr[lane + 32];
        v0 += x0; v1 += x1;
        w0 = fmaf(x0, a, w0); w1 = fmaf(x1, a, w1);
    }
    float inv = 1.f / fmaxf((float)(e - s), 1.f);
    float* o = g_agg + (size_t)node * 128;
    o[lane]      = v0 * inv;
    o[lane + 32] = v1 * inv;
    o[lane + 64] = w0 * inv;
    o[lane + 96] = w1 * inv;
}

// ---------------- GEMM1: h = relu(agg@W1 + b1), fused BN stats -------------
#define G1_SMEM_FLOATS (128*132 + 128*128)
__global__ __launch_bounds__(256, 1)
void gemm1_kernel(const float* __restrict__ W1, const float* __restrict__ b1) {
    extern __shared__ float sm[];
    float* As = sm;               // [k=128][m pitch 132]
    float* Bs = sm + 128 * 132;   // [k=128][n=128]
    __shared__ float ssum[128], ssq[128];

    int tid = threadIdx.x;
    int rowbase = blockIdx.x * 128;
    int colbase = blockIdx.y * 128;

    if (tid < 128) { ssum[tid] = 0.f; ssq[tid] = 0.f; }

    // A: agg tile transposed into smem (already mean-divided).
    #pragma unroll
    for (int i = 0; i < 64; i++) {
        int idx = i * 256 + tid;
        int m = idx >> 7;
        int k = idx & 127;
        int r = rowbase + m;
        float v = (r < N_NODES) ? g_agg[(size_t)r * 128 + k] : 0.f;
        As[k * 132 + m] = v;
    }
    // B: W1 tile, float4 copy.
    #pragma unroll
    for (int i = 0; i < 16; i++) {
        int idx = i * 256 + tid;
        int k = idx >> 5;
        int c4 = idx & 31;
        *(float4*)&Bs[k * 128 + c4 * 4] =
            *(const float4*)&W1[(size_t)k * MID + colbase + c4 * 4];
    }
    __syncthreads();

    int warp = tid >> 5, lane = tid & 31;
    int warpM = warp & 3, warpN = warp >> 2;      // warps 4x2
    int mp = lane >> 3,  np = lane & 7;           // lanes 4x8
    int tm = warpM * 32 + mp * 8;
    int tn = warpN * 64 + np * 8;

    unsigned long long acc2[4][8];
    #pragma unroll
    for (int i = 0; i < 4; i++)
        #pragma unroll
        for (int j = 0; j < 8; j++) acc2[i][j] = 0ull;

    #pragma unroll 4
    for (int k = 0; k < 128; k++) {
        ulonglong2 A0 = *(const ulonglong2*)&As[k * 132 + tm];
        ulonglong2 A1 = *(const ulonglong2*)&As[k * 132 + tm + 4];
        unsigned long long ap[4] = {A0.x, A0.y, A1.x, A1.y};
        float4 b0 = *(const float4*)&Bs[k * 128 + tn];
        float4 b1v = *(const float4*)&Bs[k * 128 + tn + 4];
        unsigned long long bp[8] = {dup2(b0.x), dup2(b0.y), dup2(b0.z), dup2(b0.w),
                                    dup2(b1v.x), dup2(b1v.y), dup2(b1v.z), dup2(b1v.w)};
        #pragma unroll
        for (int i = 0; i < 4; i++)
            #pragma unroll
            for (int j = 0; j < 8; j++) ffma2(acc2[i][j], ap[i], bp[j]);
    }

    float acc[8][8];
    #pragma unroll
    for (int i = 0; i < 4; i++)
        #pragma unroll
        for (int j = 0; j < 8; j++)
            unpack2(acc2[i][j], acc[2 * i][j], acc[2 * i + 1][j]);

    float bb[8];
    #pragma unroll
    for (int j = 0; j < 8; j++) bb[j] = b1[colbase + tn + j];

    float s_[8], q_[8];
    #pragma unroll
    for (int j = 0; j < 8; j++) { s_[j] = 0.f; q_[j] = 0.f; }

    #pragma unroll
    for (int i = 0; i < 8; i++) {
        int r = rowbase + tm + i;
        float v[8];
        #pragma unroll
        for (int j = 0; j < 8; j++) v[j] = fmaxf(acc[i][j] + bb[j], 0.f);
        if (r < N_NODES) {
            float* hp = &g_h[(size_t)r * MID + colbase + tn];
            *(float4*)hp       = make_float4(v[0], v[1], v[2], v[3]);
            *(float4*)(hp + 4) = make_float4(v[4], v[5], v[6], v[7]);
            #pragma unroll
            for (int j = 0; j < 8; j++) { s_[j] += v[j]; q_[j] += v[j] * v[j]; }
        }
    }
    #pragma unroll
    for (int j = 0; j < 8; j++) {
        s_[j] += __shfl_xor_sync(0xFFFFFFFFu, s_[j], 8);
        s_[j] += __shfl_xor_sync(0xFFFFFFFFu, s_[j], 16);
        q_[j] += __shfl_xor_sync(0xFFFFFFFFu, q_[j], 8);
        q_[j] += __shfl_xor_sync(0xFFFFFFFFu, q_[j], 16);
    }
    __syncthreads();   // ssum/ssq init visible
    if (mp == 0) {
        #pragma unroll
        for (int j = 0; j < 8; j++) {
            atomicAdd(&ssum[tn + j], s_[j]);
            atomicAdd(&ssq[tn + j],  q_[j]);
        }
    }
    __syncthreads();
    if (tid < 128) {
        atomicAdd(&P_COLSUM()[colbase + tid], ssum[tid]);
        atomicAdd(&P_COLSQ()[colbase + tid],  ssq[tid]);
    }
}

// ---------------- finalize: BN fold into W2', b2' --------------------------
__global__ void finalize_kernel(const float* __restrict__ gamma,
                                const float* __restrict__ beta,
                                const float* __restrict__ W2,
                                const float* __restrict__ b2) {
    __shared__ float s_sm[MID], t_sm[MID];
    int tid = threadIdx.x;  // 256
    float mu  = P_COLSUM()[tid] * (1.f / N_NODES);
    float var = P_COLSQ()[tid]  * (1.f / N_NODES) - mu * mu;
    float s = gamma[tid] * rsqrtf(var + BN_EPS);
    float t = beta[tid] - mu * s;
    s_sm[tid] = s; t_sm[tid] = t;
    __syncthreads();
    #pragma unroll
    for (int i = 0; i < 64; i++) {
        int idx = i * 256 + tid;            // 16384 = 256x64
        g_W2p[idx] = W2[idx] * s_sm[idx >> 6];
    }
    if (tid < OUT_F) {
        float acc = b2[tid];
        for (int j = 0; j < MID; j++) acc += t_sm[j] * W2[j * OUT_F + tid];
        g_b2p[tid] = acc;
    }
}

// ---------------- GEMM2: out = h @ W2p + b2p -------------------------------
#define G2_SMEM_FLOATS (256*132 + 256*64 + 64)
__global__ __launch_bounds__(256, 1)
void gemm2_kernel(float* __restrict__ out) {
    extern __shared__ float sm[];
    float* As = sm;               // [k=256][m pitch 132]
    float* Bs = sm + 256 * 132;   // [k=256][n=64]
    float* bb = Bs + 256 * 64;    // [64]
    int tid = threadIdx.x;
    int rowbase = blockIdx.x * 128;

    #pragma unroll
    for (int i = 0; i < 64; i++) {
        int idx = i * 256 + tid;
        int m = idx >> 7;
        int k2 = idx & 127;
        int r = rowbase + m;
        float2 v = (r < N_NODES) ? *(const float2*)&g_h[(size_t)r * MID + k2 * 2]
                                 : make_float2(0.f, 0.f);
        As[(k2 * 2)     * 132 + m] = v.x;
        As[(k2 * 2 + 1) * 132 + m] = v.y;
    }
    #pragma unroll
    for (int i = 0; i < 16; i++) {
        int idx = i * 256 + tid;
        *(float4*)&Bs[idx * 4] = *(const float4*)&g_W2p[idx * 4];
    }
    if (tid < OUT_F) bb[tid] = g_b2p[tid];
    __syncthreads();

    int warp = tid >> 5, lane = tid & 31;
    int warpM = warp & 3, warpN = warp >> 2;
    int mp = lane >> 3,  np = lane & 7;
    int tm = warpM * 32 + mp * 8;
    int tn = warpN * 32 + np * 4;

    unsigned long long acc2[4][4];
    #pragma unroll
    for (int i = 0; i < 4; i++)
        #pragma unroll
        for (int j = 0; j < 4; j++) acc2[i][j] = 0ull;

    #pragma unroll 4
    for (int k = 0; k < 256; k++) {
        ulonglong2 A0 = *(const ulonglong2*)&As[k * 132 + tm];
        ulonglong2 A1 = *(const ulonglong2*)&As[k * 132 + tm + 4];
        unsigned long long ap[4] = {A0.x, A0.y, A1.x, A1.y};
        float4 b0 = *(const float4*)&Bs[k * 64 + tn];
        unsigned long long bp[4] = {dup2(b0.x), dup2(b0.y), dup2(b0.z), dup2(b0.w)};
        #pragma unroll
        for (int i = 0; i < 4; i++)
            #pragma unroll
            for (int j = 0; j < 4; j++) ffma2(acc2[i][j], ap[i], bp[j]);
    }

    float acc[8][4];
    #pragma unroll
    for (int i = 0; i < 4; i++)
        #pragma unroll
        for (int j = 0; j < 4; j++)
            unpack2(acc2[i][j], acc[2 * i][j], acc[2 * i + 1][j]);

    float4 bv = make_float4(bb[tn], bb[tn + 1], bb[tn + 2], bb[tn + 3]);
    #pragma unroll
    for (int i = 0; i < 8; i++) {
        int r = rowbase + tm + i;
        if (r < N_NODES) {
            float4 o = make_float4(acc[i][0] + bv.x, acc[i][1] + bv.y,
                                   acc[i][2] + bv.z, acc[i][3] + bv.w);
            *(float4*)&out[(size_t)r * OUT_F + tn] = o;
        }
    }
}

// ---------------- launch ---------------------------------------------------
extern "C" void kernel_launch(void* const* d_in, const int* in_sizes, int n_in,
                              void* d_out, int out_size) {
    int ix = -1, iei = -1, iea = -1, iW1 = -1, iW2 = -1, ib2 = -1;
    int p256[3]; int n256 = 0;
    for (int i = 0; i < n_in; i++) {
        switch (in_sizes[i]) {
            case 6400000: ix  = i; break;
            case 2560000: iei = i; break;
            case 1280000: iea = i; break;
            case 32768:   iW1 = i; break;
            case 16384:   iW2 = i; break;
            case 64:      ib2 = i; break;
            case 256:     if (n256 < 3) p256[n256++] = i; break;
            default: break;
        }
    }
    int ib1, igamma, ibeta;
    if (n_in > 0 && in_sizes[0] == 6400000) { ib1 = p256[0]; igamma = p256[1]; ibeta = p256[2]; }
    else                                    { ib1 = p256[0]; ibeta  = p256[1]; igamma = p256[2]; }

    const float* x     = (const float*)d_in[ix];
    const void*  ei    = d_in[iei];
    const float* ea    = (const float*)d_in[iea];
    const float* W1    = (const float*)d_in[iW1];
    const float* b1    = (const float*)d_in[ib1];
    const float* gamma = (const float*)d_in[igamma];
    const float* beta  = (const float*)d_in[ibeta];
    const float* W2    = (const float*)d_in[iW2];
    const float* b2    = (const float*)d_in[ib2];
    float* out = (float*)d_out;

    cudaFuncSetAttribute(gemm1_kernel, cudaFuncAttributeMaxDynamicSharedMemorySize,
                         G1_SMEM_FLOATS * (int)sizeof(float));
    cudaFuncSetAttribute(gemm2_kernel, cudaFuncAttributeMaxDynamicSharedMemorySize,
                         G2_SMEM_FLOATS * (int)sizeof(float));

    void* p;
    cudaGetSymbolAddress(&p, g_zero);
    cudaMemsetAsync(p, 0, sizeof(unsigned int) * (2 * N_NODES + 512));

    detect_kernel<<<1, 32>>>((const int*)ei);

    hist_kernel<<<(E_EDGES + 255) / 256, 256>>>(ei);
    scanP_kernel<<<SCAN_NB, SCAN_BLK>>>();
    scanT_kernel<<<1, 256>>>();
    scanF_kernel<<<SCAN_NB, SCAN_BLK>>>();
    scatter_kernel<<<(E_EDGES + 255) / 256, 256>>>(ei, ea);
    agg_kernel<<<(N_NODES * 32 + 255) / 256, 256>>>(x);

    dim3 g1((N_NODES + 127) / 128, MID / 128);
    gemm1_kernel<<<g1, 256, G1_SMEM_FLOATS * sizeof(float)>>>(W1, b1);

    finalize_kernel<<<1, 256>>>(gamma, beta, W2, b2);

    gemm2_kernel<<<(N_NODES + 127) / 128, 256, G2_SMEM_FLOATS * sizeof(float)>>>(out);
}

// round 5
// speedup vs baseline: 1.3419x; 1.0018x over previous
#include <cuda_runtime.h>
#include <cstdint>

#define N_NODES 100000
#define E_EDGES 1280000
#define M_PAD   100096              // N rounded up to 128
#define C_IN    64
#define MID     256
#define OUT_F   64
#define BN_EPS  1e-5f

// ---------------- scratch (static device memory) ---------------------------
// zero-region (single memset): cnt[N] | off[N] | colsum[256] | colsq[256]
__device__ unsigned int g_zero[2 * N_NODES + 512];
#define P_CNT()    ((int*)g_zero)
#define P_OFF()    (((int*)g_zero) + N_NODES)
#define P_COLSUM() ((float*)(((int*)g_zero) + 2 * N_NODES))
#define P_COLSQ()  ((float*)(((int*)g_zero) + 2 * N_NODES + 256))

__device__ int   g_start[N_NODES + 1];            // CSR offsets
__device__ int2  g_edge[E_EDGES];                 // row-sorted (col, attr-bits)
__device__ float g_agg[(size_t)N_NODES * 128];    // mean-aggregated features
__device__ float g_hT[(size_t)MID * M_PAD];       // h transposed [MID][M_PAD]
__device__ float g_W2p[MID * OUT_F];              // s-scaled W2
__device__ float g_b2p[OUT_F];
__device__ int   g_idx64;                         // 1 if edge_index is int64

// ---------------- packed fp32 helpers (Blackwell FFMA2) --------------------
__device__ __forceinline__ unsigned long long dup2(float v) {
    unsigned long long r;
    asm("mov.b64 %0, {%1, %1};" : "=l"(r) : "f"(v));
    return r;
}
__device__ __forceinline__ void ffma2(unsigned long long& d,
                                      unsigned long long a,
                                      unsigned long long b) {
    asm("fma.rn.f32x2 %0, %1, %2, %0;" : "+l"(d) : "l"(a), "l"(b));
}
__device__ __forceinline__ void unpack2(unsigned long long v, float& lo, float& hi) {
    asm("mov.b64 {%0, %1}, %2;" : "=f"(lo), "=f"(hi) : "l"(v));
}

// ---------------- dtype probe: int64 vs int32 edge_index -------------------
__global__ void detect_kernel(const int* __restrict__ ei32) {
    if (threadIdx.x == 0) {
        int all_zero = 1;
        #pragma unroll
        for (int i = 0; i < 16; i++)
            if (ei32[2 * i + 1] != 0) all_zero = 0;
        g_idx64 = all_zero;
    }
}

__device__ __forceinline__ int load_idx(const void* ei, size_t pos) {
    return g_idx64 ? (int)((const long long*)ei)[pos] : ((const int*)ei)[pos];
}

// ---------------- 1) histogram --------------------------------------------
__global__ void hist_kernel(const void* __restrict__ ei) {
    int e = blockIdx.x * blockDim.x + threadIdx.x;
    if (e >= E_EDGES) return;
    int row = load_idx(ei, e);
    if ((unsigned)row < N_NODES) atomicAdd(&P_CNT()[row], 1);
}

// ---------------- 2) single-block exclusive scan ---------------------------
__global__ __launch_bounds__(1024)
void scan_kernel() {
    __shared__ int wsum[32], woff[32];
    __shared__ int carry_s, wtot_s;
    int tid = threadIdx.x, lane = tid & 31, wid = tid >> 5;
    if (tid == 0) carry_s = 0;
    __syncthreads();
    const int* cnt = P_CNT();
    #pragma unroll 1
    for (int c = 0; c < 25; c++) {          // 25 * 4096 = 102400 >= 100000
        int base = c * 4096 + tid * 4;
        int4 v;
        v.x = (base     < N_NODES) ? cnt[base]     : 0;
        v.y = (base + 1 < N_NODES) ? cnt[base + 1] : 0;
        v.z = (base + 2 < N_NODES) ? cnt[base + 2] : 0;
        v.w = (base + 3 < N_NODES) ? cnt[base + 3] : 0;
        int s = v.x + v.y + v.z + v.w;
        int p = s;
        #pragma unroll
        for (int o = 1; o < 32; o <<= 1) {
            int t = __shfl_up_sync(0xFFFFFFFFu, p, o);
            if (lane >= o) p += t;
        }
        if (lane == 31) wsum[wid] = p;
        __syncthreads();
        if (wid == 0) {
            int t = wsum[lane];
            int q = t;
            #pragma unroll
            for (int o = 1; o < 32; o <<= 1) {
                int u = __shfl_up_sync(0xFFFFFFFFu, q, o);
                if (lane >= o) q += u;
            }
            woff[lane] = q - t;
            if (lane == 31) wtot_s = q;
        }
        __syncthreads();
        int excl = carry_s + woff[wid] + (p - s);
        if (base     < N_NODES) g_start[base]     = excl;
        if (base + 1 < N_NODES) g_start[base + 1] = excl + v.x;
        if (base + 2 < N_NODES) g_start[base + 2] = excl + v.x + v.y;
        if (base + 3 < N_NODES) g_start[base + 3] = excl + v.x + v.y + v.z;
        __syncthreads();
        if (tid == 0) carry_s += wtot_s;
        __syncthreads();
    }
    if (tid == 0) g_start[N_NODES] = carry_s;
}

// ---------------- 3) scatter into row-sorted order (packed int2) -----------
__global__ void scatter_kernel(const void* __restrict__ ei,
                               const float* __restrict__ ea) {
    int e = blockIdx.x * blockDim.x + threadIdx.x;
    if (e >= E_EDGES) return;
    int row = load_idx(ei, e);
    int col = load_idx(ei, (size_t)E_EDGES + e);
    if ((unsigned)row >= N_NODES || (unsigned)col >= N_NODES) return;
    int p = g_start[row] + atomicAdd(&P_OFF()[row], 1);
    g_edge[p] = make_int2(col, __float_as_int(ea[e]));
}

// ---------------- 4) warp-per-node gather aggregation ----------------------
// Edge metadata loaded coalesced 32-at-a-time, broadcast via shfl.
__global__ __launch_bounds__(256)
void agg_kernel(const float* __restrict__ x) {
    int node = (blockIdx.x * blockDim.x + threadIdx.x) >> 5;
    int lane = threadIdx.x & 31;
    if (node >= N_NODES) return;
    int s = g_start[node];
    int e = g_start[node + 1];
    float v0a = 0.f, v1a = 0.f, w0a = 0.f, w1a = 0.f;
    float v0b = 0.f, v1b = 0.f, w0b = 0.f, w1b = 0.f;
    for (int base = s; base < e; base += 32) {
        int rem = e - base;
        int2 ed = make_int2(0, 0);
        if (lane < rem) ed = g_edge[base + lane];
        int n = rem < 32 ? rem : 32;
        int j = 0;
        #pragma unroll 1
        for (; j + 4 <= n; j += 4) {
            int   c0 = __shfl_sync(0xFFFFFFFFu, ed.x, j);
            float a0 = __int_as_float(__shfl_sync(0xFFFFFFFFu, ed.y, j));
            int   c1 = __shfl_sync(0xFFFFFFFFu, ed.x, j + 1);
            float a1 = __int_as_float(__shfl_sync(0xFFFFFFFFu, ed.y, j + 1));
            int   c2 = __shfl_sync(0xFFFFFFFFu, ed.x, j + 2);
            float a2 = __int_as_float(__shfl_sync(0xFFFFFFFFu, ed.y, j + 2));
            int   c3 = __shfl_sync(0xFFFFFFFFu, ed.x, j + 3);
            float a3 = __int_as_float(__shfl_sync(0xFFFFFFFFu, ed.y, j + 3));
            const float* x0p = x + (size_t)c0 * C_IN;
            const float* x1p = x + (size_t)c1 * C_IN;
            const float* x2p = x + (size_t)c2 * C_IN;
            const float* x3p = x + (size_t)c3 * C_IN;
            float p00 = x0p[lane], p01 = x0p[lane + 32];
            float p10 = x1p[lane], p11 = x1p[lane + 32];
            float p20 = x2p[lane], p21 = x2p[lane + 32];
            float p30 = x3p[lane], p31 = x3p[lane + 32];
            v0a += p00; v1a += p01; w0a = fmaf(p00, a0, w0a); w1a = fmaf(p01, a0, w1a);
            v0b += p10; v1b += p11; w0b = fmaf(p10, a1, w0b); w1b = fmaf(p11, a1, w1b);
            v0a += p20; v1a += p21; w0a = fmaf(p20, a2, w0a); w1a = fmaf(p21, a2, w1a);
            v0b += p30; v1b += p31; w0b = fmaf(p30, a3, w0b); w1b = fmaf(p31, a3, w1b);
        }
        #pragma unroll 1
        for (; j < n; j++) {
            int   c = __shfl_sync(0xFFFFFFFFu, ed.x, j);
            float a = __int_as_float(__shfl_sync(0xFFFFFFFFu, ed.y, j));
            const float* xr = x + (size_t)c * C_IN;
            float p0 = xr[lane], p1 = xr[lane + 32];
            v0a += p0; v1a += p1;
            w0a = fmaf(p0, a, w0a); w1a = fmaf(p1, a, w1a);
        }
    }
    float inv = 1.f / fmaxf((float)(e - s), 1.f);
    float* o = g_agg + (size_t)node * 128;
    o[lane]      = (v0a + v0b) * inv;
    o[lane + 32] = (v1a + v1b) * inv;
    o[lane + 64] = (w0a + w0b) * inv;
    o[lane + 96] = (w1a + w1b) * inv;
}

// ---------------- GEMM1: h = relu(agg@W1 + b1), fused BN stats -------------
// 128x128 tile, K=128, FFMA2 mainloop; epilogue writes h TRANSPOSED (g_hT).
#define G1_SMEM_FLOATS (128*132 + 128*128)
__global__ __launch_bounds__(256, 1)
void gemm1_kernel(const float* __restrict__ W1, const float* __restrict__ b1) {
    extern __shared__ float sm[];
    float* As = sm;               // [k=128][m pitch 132]
    float* Bs = sm + 128 * 132;   // [k=128][n=128]
    __shared__ float ssum[128], ssq[128];

    int tid = threadIdx.x;
    int rowbase = blockIdx.x * 128;
    int colbase = blockIdx.y * 128;

    if (tid < 128) { ssum[tid] = 0.f; ssq[tid] = 0.f; }

    #pragma unroll
    for (int i = 0; i < 64; i++) {
        int idx = i * 256 + tid;
        int m = idx >> 7;
        int k = idx & 127;
        int r = rowbase + m;
        float v = (r < N_NODES) ? g_agg[(size_t)r * 128 + k] : 0.f;
        As[k * 132 + m] = v;
    }
    #pragma unroll
    for (int i = 0; i < 16; i++) {
        int idx = i * 256 + tid;
        int k = idx >> 5;
        int c4 = idx & 31;
        *(float4*)&Bs[k * 128 + c4 * 4] =
            *(const float4*)&W1[(size_t)k * MID + colbase + c4 * 4];
    }
    __syncthreads();

    int warp = tid >> 5, lane = tid & 31;
    int warpM = warp & 3, warpN = warp >> 2;      // warps 4x2
    int mp = lane >> 3,  np = lane & 7;           // lanes 4x8
    int tm = warpM * 32 + mp * 8;
    int tn = warpN * 64 + np * 8;

    unsigned long long acc2[4][8];
    #pragma unroll
    for (int i = 0; i < 4; i++)
        #pragma unroll
        for (int j = 0; j < 8; j++) acc2[i][j] = 0ull;

    #pragma unroll 4
    for (int k = 0; k < 128; k++) {
        ulonglong2 A0 = *(const ulonglong2*)&As[k * 132 + tm];
        ulonglong2 A1 = *(const ulonglong2*)&As[k * 132 + tm + 4];
        unsigned long long ap[4] = {A0.x, A0.y, A1.x, A1.y};
        float4 b0 = *(const float4*)&Bs[k * 128 + tn];
        float4 b1v = *(const float4*)&Bs[k * 128 + tn + 4];
        unsigned long long bp[8] = {dup2(b0.x), dup2(b0.y), dup2(b0.z), dup2(b0.w),
                                    dup2(b1v.x), dup2(b1v.y), dup2(b1v.z), dup2(b1v.w)};
        #pragma unroll
        for (int i = 0; i < 4; i++)
            #pragma unroll
            for (int j = 0; j < 8; j++) ffma2(acc2[i][j], ap[i], bp[j]);
    }

    float acc[8][8];
    #pragma unroll
    for (int i = 0; i < 4; i++)
        #pragma unroll
        for (int j = 0; j < 8; j++)
            unpack2(acc2[i][j], acc[2 * i][j], acc[2 * i + 1][j]);

    float bb[8];
    #pragma unroll
    for (int j = 0; j < 8; j++) bb[j] = b1[colbase + tn + j];

    // relu in place
    #pragma unroll
    for (int i = 0; i < 8; i++)
        #pragma unroll
        for (int j = 0; j < 8; j++)
            acc[i][j] = fmaxf(acc[i][j] + bb[j], 0.f);

    // transposed store: row-pad region (>=N) written too (harmless)
    #pragma unroll
    for (int j = 0; j < 8; j++) {
        size_t cb = (size_t)(colbase + tn + j) * M_PAD + rowbase + tm;
        *(float4*)&g_hT[cb]     = make_float4(acc[0][j], acc[1][j], acc[2][j], acc[3][j]);
        *(float4*)&g_hT[cb + 4] = make_float4(acc[4][j], acc[5][j], acc[6][j], acc[7][j]);
    }

    // BN stats over valid rows only
    float s_[8], q_[8];
    #pragma unroll
    for (int j = 0; j < 8; j++) { s_[j] = 0.f; q_[j] = 0.f; }
    #pragma unroll
    for (int i = 0; i < 8; i++) {
        if (rowbase + tm + i < N_NODES) {
            #pragma unroll
            for (int j = 0; j < 8; j++) {
                s_[j] += acc[i][j];
                q_[j] += acc[i][j] * acc[i][j];
            }
        }
    }
    #pragma unroll
    for (int j = 0; j < 8; j++) {
        s_[j] += __shfl_xor_sync(0xFFFFFFFFu, s_[j], 8);
        s_[j] += __shfl_xor_sync(0xFFFFFFFFu, s_[j], 16);
        q_[j] += __shfl_xor_sync(0xFFFFFFFFu, q_[j], 8);
        q_[j] += __shfl_xor_sync(0xFFFFFFFFu, q_[j], 16);
    }
    __syncthreads();   // ssum/ssq init visible
    if (mp == 0) {
        #pragma unroll
        for (int j = 0; j < 8; j++) {
            atomicAdd(&ssum[tn + j], s_[j]);
            atomicAdd(&ssq[tn + j],  q_[j]);
        }
    }
    __syncthreads();
    if (tid < 128) {
        atomicAdd(&P_COLSUM()[colbase + tid], ssum[tid]);
        atomicAdd(&P_COLSQ()[colbase + tid],  ssq[tid]);
    }
}

// ---------------- finalize: BN fold into W2', b2' --------------------------
__global__ void finalize_kernel(const float* __restrict__ gamma,
                                const float* __restrict__ beta,
                                const float* __restrict__ W2,
                                const float* __restrict__ b2) {
    __shared__ float s_sm[MID], t_sm[MID];
    int tid = threadIdx.x;  // 256
    float mu  = P_COLSUM()[tid] * (1.f / N_NODES);
    float var = P_COLSQ()[tid]  * (1.f / N_NODES) - mu * mu;
    float s = gamma[tid] * rsqrtf(var + BN_EPS);
    float t = beta[tid] - mu * s;
    s_sm[tid] = s; t_sm[tid] = t;
    __syncthreads();
    #pragma unroll
    for (int i = 0; i < 64; i++) {
        int idx = i * 256 + tid;            // 16384 = 256x64
        g_W2p[idx] = W2[idx] * s_sm[idx >> 6];
    }
    if (tid < OUT_F) {
        float acc = b2[tid];
        for (int j = 0; j < MID; j++) acc += t_sm[j] * W2[j * OUT_F + tid];
        g_b2p[tid] = acc;
    }
}

// ---------------- GEMM2: out = h @ W2p + b2p (A from g_hT, direct copy) ----
#define G2_SMEM_FLOATS (256*128 + 256*64 + 64)
__global__ __launch_bounds__(256, 1)
void gemm2_kernel(float* __restrict__ out) {
    extern __shared__ float sm[];
    float* As = sm;               // [k=256][m=128] pitch 128
    float* Bs = sm + 256 * 128;   // [k=256][n=64]
    float* bb = Bs + 256 * 64;    // [64]
    int tid = threadIdx.x;
    int rowbase = blockIdx.x * 128;

    // A: direct coalesced copy from transposed h
    #pragma unroll
    for (int i = 0; i < 32; i++) {
        int idx = i * 256 + tid;          // 8192 float4 = 256x128 floats
        int k  = idx >> 5;
        int m4 = idx & 31;
        *(float4*)&As[k * 128 + m4 * 4] =
            *(const float4*)&g_hT[(size_t)k * M_PAD + rowbase + m4 * 4];
    }
    // B: W2p full, float4 copy
    #pragma unroll
    for (int i = 0; i < 16; i++) {
        int idx = i * 256 + tid;
        *(float4*)&Bs[idx * 4] = *(const float4*)&g_W2p[idx * 4];
    }
    if (tid < OUT_F) bb[tid] = g_b2p[tid];
    __syncthreads();

    int warp = tid >> 5, lane = tid & 31;
    int warpM = warp & 3, warpN = warp >> 2;
    int mp = lane >> 3,  np = lane & 7;
    int tm = warpM * 32 + mp * 8;
    int tn = warpN * 32 + np * 4;

    unsigned long long acc2[4][4];
    #pragma unroll
    for (int i = 0; i < 4; i++)
        #pragma unroll
        for (int j = 0; j < 4; j++) acc2[i][j] = 0ull;

    #pragma unroll 4
    for (int k = 0; k < 256; k++) {
        ulonglong2 A0 = *(const ulonglong2*)&As[k * 128 + tm];
        ulonglong2 A1 = *(const ulonglong2*)&As[k * 128 + tm + 4];
        unsigned long long ap[4] = {A0.x, A0.y, A1.x, A1.y};
        float4 b0 = *(const float4*)&Bs[k * 64 + tn];
        unsigned long long bp[4] = {dup2(b0.x), dup2(b0.y), dup2(b0.z), dup2(b0.w)};
        #pragma unroll
        for (int i = 0; i < 4; i++)
            #pragma unroll
            for (int j = 0; j < 4; j++) ffma2(acc2[i][j], ap[i], bp[j]);
    }

    float acc[8][4];
    #pragma unroll
    for (int i = 0; i < 4; i++)
        #pragma unroll
        for (int j = 0; j < 4; j++)
            unpack2(acc2[i][j], acc[2 * i][j], acc[2 * i + 1][j]);

    float4 bv = make_float4(bb[tn], bb[tn + 1], bb[tn + 2], bb[tn + 3]);
    #pragma unroll
    for (int i = 0; i < 8; i++) {
        int r = rowbase + tm + i;
        if (r < N_NODES) {
            float4 o = make_float4(acc[i][0] + bv.x, acc[i][1] + bv.y,
                                   acc[i][2] + bv.z, acc[i][3] + bv.w);
            *(float4*)&out[(size_t)r * OUT_F + tn] = o;
        }
    }
}

// ---------------- launch ---------------------------------------------------
extern "C" void kernel_launch(void* const* d_in, const int* in_sizes, int n_in,
                              void* d_out, int out_size) {
    int ix = -1, iei = -1, iea = -1, iW1 = -1, iW2 = -1, ib2 = -1;
    int p256[3]; int n256 = 0;
    for (int i = 0; i < n_in; i++) {
        switch (in_sizes[i]) {
            case 6400000: ix  = i; break;
            case 2560000: iei = i; break;
            case 1280000: iea = i; break;
            case 32768:   iW1 = i; break;
            case 16384:   iW2 = i; break;
            case 64:      ib2 = i; break;
            case 256:     if (n256 < 3) p256[n256++] = i; break;
            default: break;
        }
    }
    int ib1, igamma, ibeta;
    if (n_in > 0 && in_sizes[0] == 6400000) { ib1 = p256[0]; igamma = p256[1]; ibeta = p256[2]; }
    else                                    { ib1 = p256[0]; ibeta  = p256[1]; igamma = p256[2]; }

    const float* x     = (const float*)d_in[ix];
    const void*  ei    = d_in[iei];
    const float* ea    = (const float*)d_in[iea];
    const float* W1    = (const float*)d_in[iW1];
    const float* b1    = (const float*)d_in[ib1];
    const float* gamma = (const float*)d_in[igamma];
    const float* beta  = (const float*)d_in[ibeta];
    const float* W2    = (const float*)d_in[iW2];
    const float* b2    = (const float*)d_in[ib2];
    float* out = (float*)d_out;

    cudaFuncSetAttribute(gemm1_kernel, cudaFuncAttributeMaxDynamicSharedMemorySize,
                         G1_SMEM_FLOATS * (int)sizeof(float));
    cudaFuncSetAttribute(gemm2_kernel, cudaFuncAttributeMaxDynamicSharedMemorySize,
                         G2_SMEM_FLOATS * (int)sizeof(float));

    void* p;
    cudaGetSymbolAddress(&p, g_zero);
    cudaMemsetAsync(p, 0, sizeof(unsigned int) * (2 * N_NODES + 512));

    detect_kernel<<<1, 32>>>((const int*)ei);
    hist_kernel<<<(E_EDGES + 255) / 256, 256>>>(ei);
    scan_kernel<<<1, 1024>>>();
    scatter_kernel<<<(E_EDGES + 255) / 256, 256>>>(ei, ea);
    agg_kernel<<<(N_NODES * 32 + 255) / 256, 256>>>(x);

    dim3 g1((N_NODES + 127) / 128, MID / 128);
    gemm1_kernel<<<g1, 256, G1_SMEM_FLOATS * sizeof(float)>>>(W1, b1);
    finalize_kernel<<<1, 256>>>(gamma, beta, W2, b2);
    gemm2_kernel<<<(N_NODES + 127) / 128, 256, G2_SMEM_FLOATS * sizeof(float)>>>(out);
}